// round 3
// baseline (speedup 1.0000x reference)
#include <cuda_runtime.h>
#include <stdint.h>

#define TB 64          // batch rows per CTA
#define THREADS 256
#define D 64
#define H 128

// Shared-memory layout (floats):
//  Xs : 64 x 68            (gathered input tile, stride 68)
//  Ws : 8704               (weight tile: layer1/2 use [64][132], layer3 uses [128][68])
//  H1 : 64 x 132
//  H2 : 64 x 132
#define XS_STRIDE 68
#define WS_STRIDE 132
#define W3_STRIDE 68
#define XS_OFF    0
#define WS_OFF    (64*XS_STRIDE)            // 4352
#define H1_OFF    (WS_OFF + 8704)           // 13056
#define H2_OFF    (H1_OFF + 64*WS_STRIDE)   // 21504
#define SMEM_FLOATS (H2_OFF + 64*WS_STRIDE) // 29952 -> 119808 bytes

struct Params {
    const float* w1[5]; const float* b1[5];
    const float* w2[5]; const float* b2[5];
    const float* w3[5]; const float* b3[5];
};

struct NodeInfo { int gi, row, n, out, nb[6]; };

// 21 nodes: group id, row within group, neighbor count, output joint, neighbor list
__constant__ NodeInfo c_nodes[21] = {
    {0,0,6, 0,{0,1,5,9,13,17}},
    {1,0,5, 5,{0,5,6,1,9,0}},
    {1,1,5, 9,{0,9,10,5,13,0}},
    {1,2,5,13,{0,13,14,9,17,0}},
    {2,0,4, 1,{0,1,2,5,0,0}},
    {2,1,4,17,{0,17,18,13,0,0}},
    {3,0,3, 2,{1,2,3,0,0,0}},
    {3,1,3, 3,{2,3,4,0,0,0}},
    {3,2,3, 6,{5,6,7,0,0,0}},
    {3,3,3, 7,{6,7,8,0,0,0}},
    {3,4,3,10,{9,10,11,0,0,0}},
    {3,5,3,11,{10,11,12,0,0,0}},
    {3,6,3,14,{13,14,15,0,0,0}},
    {3,7,3,15,{14,15,16,0,0,0}},
    {3,8,3,18,{17,18,19,0,0,0}},
    {3,9,3,19,{18,19,20,0,0,0}},
    {4,0,2, 4,{3,4,0,0,0,0}},
    {4,1,2, 8,{7,8,0,0,0,0}},
    {4,2,2,12,{11,12,0,0,0,0}},
    {4,3,2,16,{15,16,0,0,0,0}},
    {4,4,2,20,{19,20,0,0,0,0}},
};

__global__ void __launch_bounds__(THREADS, 1)
mp_mlp_kernel(const float* __restrict__ x, Params p, float* __restrict__ out, int B)
{
    extern __shared__ float sm[];
    float* Xs  = sm + XS_OFF;
    float* Ws  = sm + WS_OFF;
    float* H1s = sm + H1_OFF;
    float* H2s = sm + H2_OFF;

    const NodeInfo nd = c_nodes[blockIdx.y];
    const int b0  = blockIdx.x * TB;
    const int tid = threadIdx.x;
    const int tx  = tid & 15;      // column group
    const int ty  = tid >> 4;      // row group
    const int r0  = ty * 4;        // 4 rows per thread
    const int c0  = tx * 8;        // 8 cols per thread (layers 1/2)

    const float* W1 = p.w1[nd.gi] + (size_t)nd.row * nd.n * D * H;
    const float* B1 = p.b1[nd.gi] + nd.row * H;
    const float* W2 = p.w2[nd.gi] + (size_t)nd.row * H * H;
    const float* B2 = p.b2[nd.gi] + nd.row * H;
    const float* W3 = p.w3[nd.gi] + (size_t)nd.row * H * D;
    const float* B3 = p.b3[nd.gi] + nd.row * D;

    float acc[4][8];
    #pragma unroll
    for (int i = 0; i < 4; ++i)
        #pragma unroll
        for (int j = 0; j < 8; ++j) acc[i][j] = 0.f;

    // ================= layer 1: [64, n*64] @ [n*64, 128] =================
    for (int t = 0; t < nd.n; ++t) {
        const int nb = nd.nb[t];
        // gathered X tile: Xs[64][64]
        #pragma unroll
        for (int i = 0; i < 4; ++i) {
            int idx = tid + i * 256;          // 0..1023
            int row = idx >> 4;
            int c4  = (idx & 15) << 2;
            float4 v = *(const float4*)(x + ((size_t)(b0 + row) * 21 + nb) * D + c4);
            *(float4*)(Xs + row * XS_STRIDE + c4) = v;
        }
        // W1 K-tile: Ws[64][128]
        #pragma unroll
        for (int i = 0; i < 8; ++i) {
            int idx = tid + i * 256;          // 0..2047
            int kk  = idx >> 5;
            int c4  = (idx & 31) << 2;
            float4 v = *(const float4*)(W1 + (size_t)(t * 64 + kk) * H + c4);
            *(float4*)(Ws + kk * WS_STRIDE + c4) = v;
        }
        __syncthreads();
        #pragma unroll 8
        for (int kk = 0; kk < 64; ++kk) {
            float xr[4];
            #pragma unroll
            for (int i = 0; i < 4; ++i) xr[i] = Xs[(r0 + i) * XS_STRIDE + kk];
            float4 wa = *(const float4*)(Ws + kk * WS_STRIDE + c0);
            float4 wb = *(const float4*)(Ws + kk * WS_STRIDE + c0 + 4);
            float w[8] = {wa.x, wa.y, wa.z, wa.w, wb.x, wb.y, wb.z, wb.w};
            #pragma unroll
            for (int i = 0; i < 4; ++i)
                #pragma unroll
                for (int j = 0; j < 8; ++j)
                    acc[i][j] = fmaf(xr[i], w[j], acc[i][j]);
        }
        __syncthreads();
    }
    // bias + relu -> H1
    {
        float4 ba = *(const float4*)(B1 + c0);
        float4 bb = *(const float4*)(B1 + c0 + 4);
        float b[8] = {ba.x, ba.y, ba.z, ba.w, bb.x, bb.y, bb.z, bb.w};
        #pragma unroll
        for (int i = 0; i < 4; ++i)
            #pragma unroll
            for (int j = 0; j < 8; ++j)
                H1s[(r0 + i) * WS_STRIDE + c0 + j] = fmaxf(acc[i][j] + b[j], 0.f);
    }
    // (no sync needed before Ws reload: everyone passed the final sync above and
    //  only writes H1s afterward; the sync after the load publishes both.)

    // ================= layer 2: [64,128] @ [128,128] =================
    #pragma unroll
    for (int i = 0; i < 4; ++i)
        #pragma unroll
        for (int j = 0; j < 8; ++j) acc[i][j] = 0.f;

    for (int kt = 0; kt < 2; ++kt) {
        #pragma unroll
        for (int i = 0; i < 8; ++i) {
            int idx = tid + i * 256;
            int kk  = idx >> 5;
            int c4  = (idx & 31) << 2;
            float4 v = *(const float4*)(W2 + (size_t)(kt * 64 + kk) * H + c4);
            *(float4*)(Ws + kk * WS_STRIDE + c4) = v;
        }
        __syncthreads();
        #pragma unroll 8
        for (int kk = 0; kk < 64; ++kk) {
            float xr[4];
            #pragma unroll
            for (int i = 0; i < 4; ++i) xr[i] = H1s[(r0 + i) * WS_STRIDE + kt * 64 + kk];
            float4 wa = *(const float4*)(Ws + kk * WS_STRIDE + c0);
            float4 wb = *(const float4*)(Ws + kk * WS_STRIDE + c0 + 4);
            float w[8] = {wa.x, wa.y, wa.z, wa.w, wb.x, wb.y, wb.z, wb.w};
            #pragma unroll
            for (int i = 0; i < 4; ++i)
                #pragma unroll
                for (int j = 0; j < 8; ++j)
                    acc[i][j] = fmaf(xr[i], w[j], acc[i][j]);
        }
        __syncthreads();
    }
    // bias + relu -> H2
    {
        float4 ba = *(const float4*)(B2 + c0);
        float4 bb = *(const float4*)(B2 + c0 + 4);
        float b[8] = {ba.x, ba.y, ba.z, ba.w, bb.x, bb.y, bb.z, bb.w};
        #pragma unroll
        for (int i = 0; i < 4; ++i)
            #pragma unroll
            for (int j = 0; j < 8; ++j)
                H2s[(r0 + i) * WS_STRIDE + c0 + j] = fmaxf(acc[i][j] + b[j], 0.f);
    }

    // ================= layer 3: [64,128] @ [128,64] =================
    // W3 tile: Ws[128][64] (stride 68)
    #pragma unroll
    for (int i = 0; i < 8; ++i) {
        int idx = tid + i * 256;      // 0..2047
        int kk  = idx >> 4;
        int c4  = (idx & 15) << 2;
        float4 v = *(const float4*)(W3 + (size_t)kk * D + c4);
        *(float4*)(Ws + kk * W3_STRIDE + c4) = v;
    }
    __syncthreads();   // publishes Ws(W3) and H2s

    float a3[4][4];
    #pragma unroll
    for (int i = 0; i < 4; ++i)
        #pragma unroll
        for (int j = 0; j < 4; ++j) a3[i][j] = 0.f;

    const int c3 = tx * 4;   // 4 output cols per thread (64 cols total)
    #pragma unroll 8
    for (int kk = 0; kk < 128; ++kk) {
        float xr[4];
        #pragma unroll
        for (int i = 0; i < 4; ++i) xr[i] = H2s[(r0 + i) * WS_STRIDE + kk];
        float4 w = *(const float4*)(Ws + kk * W3_STRIDE + c3);
        #pragma unroll
        for (int i = 0; i < 4; ++i) {
            a3[i][0] = fmaf(xr[i], w.x, a3[i][0]);
            a3[i][1] = fmaf(xr[i], w.y, a3[i][1]);
            a3[i][2] = fmaf(xr[i], w.z, a3[i][2]);
            a3[i][3] = fmaf(xr[i], w.w, a3[i][3]);
        }
    }

    float4 b3v = *(const float4*)(B3 + c3);
    #pragma unroll
    for (int i = 0; i < 4; ++i) {
        float4 o;
        o.x = a3[i][0] + b3v.x;
        o.y = a3[i][1] + b3v.y;
        o.z = a3[i][2] + b3v.z;
        o.w = a3[i][3] + b3v.w;
        *(float4*)(out + ((size_t)(b0 + r0 + i) * 21 + nd.out) * D + c3) = o;
    }
}

extern "C" void kernel_launch(void* const* d_in, const int* in_sizes, int n_in,
                              void* d_out, int out_size)
{
    const float* x = (const float*)d_in[0];
    Params p;
    for (int g = 0; g < 5; ++g) {
        p.w1[g] = (const float*)d_in[1 + 6 * g + 0];
        p.b1[g] = (const float*)d_in[1 + 6 * g + 1];
        p.w2[g] = (const float*)d_in[1 + 6 * g + 2];
        p.b2[g] = (const float*)d_in[1 + 6 * g + 3];
        p.w3[g] = (const float*)d_in[1 + 6 * g + 4];
        p.b3[g] = (const float*)d_in[1 + 6 * g + 5];
    }
    int B = in_sizes[0] / (21 * D);

    size_t smem = SMEM_FLOATS * sizeof(float);   // 119808 bytes
    cudaFuncSetAttribute(mp_mlp_kernel,
                         cudaFuncAttributeMaxDynamicSharedMemorySize, (int)smem);

    dim3 grid(B / TB, 21);
    mp_mlp_kernel<<<grid, THREADS, smem>>>(x, p, (float*)d_out, B);
}

// round 4
// speedup vs baseline: 1.3208x; 1.3208x over previous
#include <cuda_runtime.h>
#include <stdint.h>

#define TB 128         // batch rows per CTA
#define THREADS 256
#define D 64
#define H 128

// Shared-memory layout (floats):
//  Xs : 128 x 68           (gathered input tile, stride 68)
//  Ws : 8704               (weights: L1/L2 tiles [64][132]; L3 [128][68])
//  H1 : 128 x 132
//  H2 : 128 x 132
#define XS_STRIDE 68
#define WS_STRIDE 132
#define W3_STRIDE 68
#define XS_OFF    0
#define WS_OFF    (128*XS_STRIDE)           // 8704
#define H1_OFF    (WS_OFF + 8704)           // 17408
#define H2_OFF    (H1_OFF + 128*WS_STRIDE)  // 34304
#define SMEM_FLOATS (H2_OFF + 128*WS_STRIDE) // 51200 -> 204800 bytes

struct Params {
    const float* w1[5]; const float* b1[5];
    const float* w2[5]; const float* b2[5];
    const float* w3[5]; const float* b3[5];
};

struct NodeInfo { int gi, row, n, out, nb[6]; };

__constant__ NodeInfo c_nodes[21] = {
    {0,0,6, 0,{0,1,5,9,13,17}},
    {1,0,5, 5,{0,5,6,1,9,0}},
    {1,1,5, 9,{0,9,10,5,13,0}},
    {1,2,5,13,{0,13,14,9,17,0}},
    {2,0,4, 1,{0,1,2,5,0,0}},
    {2,1,4,17,{0,17,18,13,0,0}},
    {3,0,3, 2,{1,2,3,0,0,0}},
    {3,1,3, 3,{2,3,4,0,0,0}},
    {3,2,3, 6,{5,6,7,0,0,0}},
    {3,3,3, 7,{6,7,8,0,0,0}},
    {3,4,3,10,{9,10,11,0,0,0}},
    {3,5,3,11,{10,11,12,0,0,0}},
    {3,6,3,14,{13,14,15,0,0,0}},
    {3,7,3,15,{14,15,16,0,0,0}},
    {3,8,3,18,{17,18,19,0,0,0}},
    {3,9,3,19,{18,19,20,0,0,0}},
    {4,0,2, 4,{3,4,0,0,0,0}},
    {4,1,2, 8,{7,8,0,0,0,0}},
    {4,2,2,12,{11,12,0,0,0,0}},
    {4,3,2,16,{15,16,0,0,0,0}},
    {4,4,2,20,{19,20,0,0,0,0}},
};

// ---- packed f32x2 helpers (Blackwell-only FFMA2 path, PTX-exclusive) ----
__device__ __forceinline__ unsigned long long dup2(float v) {
    unsigned long long r;
    asm("mov.b64 %0, {%1, %1};" : "=l"(r) : "f"(v));
    return r;
}
__device__ __forceinline__ void fma2(unsigned long long& acc,
                                     unsigned long long a, unsigned long long b) {
    asm("fma.rn.f32x2 %0, %1, %2, %0;" : "+l"(acc) : "l"(a), "l"(b));
}
__device__ __forceinline__ void unpack2(unsigned long long v, float& lo, float& hi) {
    asm("mov.b64 {%0, %1}, %2;" : "=f"(lo), "=f"(hi) : "l"(v));
}

__global__ void __launch_bounds__(THREADS, 1)
mp_mlp_kernel(const float* __restrict__ x, Params p, float* __restrict__ out, int B)
{
    extern __shared__ float sm[];
    float* Xs  = sm + XS_OFF;
    float* Ws  = sm + WS_OFF;
    float* H1s = sm + H1_OFF;
    float* H2s = sm + H2_OFF;

    const NodeInfo nd = c_nodes[blockIdx.y];
    const int b0  = blockIdx.x * TB;
    const int tid = threadIdx.x;
    const int tx  = tid & 15;      // column group
    const int ty  = tid >> 4;      // row group
    const int r0  = ty * 8;        // 8 rows per thread
    const int c0  = tx * 8;        // 8 cols per thread (layers 1/2)

    const float* W1 = p.w1[nd.gi] + (size_t)nd.row * nd.n * D * H;
    const float* B1 = p.b1[nd.gi] + nd.row * H;
    const float* W2 = p.w2[nd.gi] + (size_t)nd.row * H * H;
    const float* B2 = p.b2[nd.gi] + nd.row * H;
    const float* W3 = p.w3[nd.gi] + (size_t)nd.row * H * D;
    const float* B3 = p.b3[nd.gi] + nd.row * D;

    // acc2[i][j] : rows r0+i, col pair (c0+2j, c0+2j+1)
    unsigned long long acc2[8][4];
    #pragma unroll
    for (int i = 0; i < 8; ++i)
        #pragma unroll
        for (int j = 0; j < 4; ++j) acc2[i][j] = 0ULL;

    // ================= layer 1: [128, n*64] @ [n*64, 128] =================
    for (int t = 0; t < nd.n; ++t) {
        const int nb = nd.nb[t];
        // gathered X tile: Xs[128][64]  (2048 float4)
        #pragma unroll
        for (int i = 0; i < 8; ++i) {
            int idx = tid + i * 256;
            int row = idx >> 4;
            int c4  = (idx & 15) << 2;
            float4 v = *(const float4*)(x + ((size_t)(b0 + row) * 21 + nb) * D + c4);
            *(float4*)(Xs + row * XS_STRIDE + c4) = v;
        }
        // W1 K-tile: Ws[64][128]  (2048 float4)
        #pragma unroll
        for (int i = 0; i < 8; ++i) {
            int idx = tid + i * 256;
            int kk  = idx >> 5;
            int c4  = (idx & 31) << 2;
            float4 v = *(const float4*)(W1 + (size_t)(t * 64 + kk) * H + c4);
            *(float4*)(Ws + kk * WS_STRIDE + c4) = v;
        }
        __syncthreads();
        #pragma unroll 2
        for (int kk = 0; kk < 64; ++kk) {
            unsigned long long x2[8];
            #pragma unroll
            for (int i = 0; i < 8; ++i) x2[i] = dup2(Xs[(r0 + i) * XS_STRIDE + kk]);
            ulonglong2 wa = *(const ulonglong2*)(Ws + kk * WS_STRIDE + c0);
            ulonglong2 wb = *(const ulonglong2*)(Ws + kk * WS_STRIDE + c0 + 4);
            unsigned long long w2[4] = {wa.x, wa.y, wb.x, wb.y};
            #pragma unroll
            for (int i = 0; i < 8; ++i)
                #pragma unroll
                for (int j = 0; j < 4; ++j)
                    fma2(acc2[i][j], x2[i], w2[j]);
        }
        __syncthreads();
    }
    // bias + relu -> H1
    {
        float4 ba = *(const float4*)(B1 + c0);
        float4 bb = *(const float4*)(B1 + c0 + 4);
        float b[8] = {ba.x, ba.y, ba.z, ba.w, bb.x, bb.y, bb.z, bb.w};
        #pragma unroll
        for (int i = 0; i < 8; ++i) {
            float h[8];
            #pragma unroll
            for (int j = 0; j < 4; ++j) {
                float lo, hi; unpack2(acc2[i][j], lo, hi);
                h[2*j]   = fmaxf(lo + b[2*j],   0.f);
                h[2*j+1] = fmaxf(hi + b[2*j+1], 0.f);
            }
            *(float4*)(H1s + (r0 + i) * WS_STRIDE + c0)     = make_float4(h[0],h[1],h[2],h[3]);
            *(float4*)(H1s + (r0 + i) * WS_STRIDE + c0 + 4) = make_float4(h[4],h[5],h[6],h[7]);
        }
    }

    // ================= layer 2: [128,128] @ [128,128] =================
    #pragma unroll
    for (int i = 0; i < 8; ++i)
        #pragma unroll
        for (int j = 0; j < 4; ++j) acc2[i][j] = 0ULL;

    for (int kt = 0; kt < 2; ++kt) {
        #pragma unroll
        for (int i = 0; i < 8; ++i) {
            int idx = tid + i * 256;
            int kk  = idx >> 5;
            int c4  = (idx & 31) << 2;
            float4 v = *(const float4*)(W2 + (size_t)(kt * 64 + kk) * H + c4);
            *(float4*)(Ws + kk * WS_STRIDE + c4) = v;
        }
        __syncthreads();   // publishes Ws(W2 tile) and (for kt=0) the H1 writes
        #pragma unroll 2
        for (int kk = 0; kk < 64; ++kk) {
            unsigned long long x2[8];
            #pragma unroll
            for (int i = 0; i < 8; ++i)
                x2[i] = dup2(H1s[(r0 + i) * WS_STRIDE + kt * 64 + kk]);
            ulonglong2 wa = *(const ulonglong2*)(Ws + kk * WS_STRIDE + c0);
            ulonglong2 wb = *(const ulonglong2*)(Ws + kk * WS_STRIDE + c0 + 4);
            unsigned long long w2[4] = {wa.x, wa.y, wb.x, wb.y};
            #pragma unroll
            for (int i = 0; i < 8; ++i)
                #pragma unroll
                for (int j = 0; j < 4; ++j)
                    fma2(acc2[i][j], x2[i], w2[j]);
        }
        __syncthreads();
    }
    // bias + relu -> H2
    {
        float4 ba = *(const float4*)(B2 + c0);
        float4 bb = *(const float4*)(B2 + c0 + 4);
        float b[8] = {ba.x, ba.y, ba.z, ba.w, bb.x, bb.y, bb.z, bb.w};
        #pragma unroll
        for (int i = 0; i < 8; ++i) {
            float h[8];
            #pragma unroll
            for (int j = 0; j < 4; ++j) {
                float lo, hi; unpack2(acc2[i][j], lo, hi);
                h[2*j]   = fmaxf(lo + b[2*j],   0.f);
                h[2*j+1] = fmaxf(hi + b[2*j+1], 0.f);
            }
            *(float4*)(H2s + (r0 + i) * WS_STRIDE + c0)     = make_float4(h[0],h[1],h[2],h[3]);
            *(float4*)(H2s + (r0 + i) * WS_STRIDE + c0 + 4) = make_float4(h[4],h[5],h[6],h[7]);
        }
    }

    // ================= layer 3: [128,128] @ [128,64] =================
    // W3 tile: Ws[128][64] (stride 68); safe: last layer-2 compute finished at
    // the final __syncthreads above.
    #pragma unroll
    for (int i = 0; i < 8; ++i) {
        int idx = tid + i * 256;      // 0..2047
        int kk  = idx >> 4;
        int c4  = (idx & 15) << 2;
        float4 v = *(const float4*)(W3 + (size_t)kk * D + c4);
        *(float4*)(Ws + kk * W3_STRIDE + c4) = v;
    }
    __syncthreads();   // publishes Ws(W3) and H2s

    unsigned long long a3[8][2];
    #pragma unroll
    for (int i = 0; i < 8; ++i) { a3[i][0] = 0ULL; a3[i][1] = 0ULL; }

    const int c3 = tx * 4;   // 4 output cols per thread
    #pragma unroll 2
    for (int kk = 0; kk < 128; ++kk) {
        unsigned long long x2[8];
        #pragma unroll
        for (int i = 0; i < 8; ++i)
            x2[i] = dup2(H2s[(r0 + i) * WS_STRIDE + kk]);
        ulonglong2 w = *(const ulonglong2*)(Ws + kk * W3_STRIDE + c3);
        #pragma unroll
        for (int i = 0; i < 8; ++i) {
            fma2(a3[i][0], x2[i], w.x);
            fma2(a3[i][1], x2[i], w.y);
        }
    }

    float4 b3v = *(const float4*)(B3 + c3);
    #pragma unroll
    for (int i = 0; i < 8; ++i) {
        float o0, o1, o2, o3;
        unpack2(a3[i][0], o0, o1);
        unpack2(a3[i][1], o2, o3);
        float4 o = make_float4(o0 + b3v.x, o1 + b3v.y, o2 + b3v.z, o3 + b3v.w);
        *(float4*)(out + ((size_t)(b0 + r0 + i) * 21 + nd.out) * D + c3) = o;
    }
}

extern "C" void kernel_launch(void* const* d_in, const int* in_sizes, int n_in,
                              void* d_out, int out_size)
{
    const float* x = (const float*)d_in[0];
    Params p;
    for (int g = 0; g < 5; ++g) {
        p.w1[g] = (const float*)d_in[1 + 6 * g + 0];
        p.b1[g] = (const float*)d_in[1 + 6 * g + 1];
        p.w2[g] = (const float*)d_in[1 + 6 * g + 2];
        p.b2[g] = (const float*)d_in[1 + 6 * g + 3];
        p.w3[g] = (const float*)d_in[1 + 6 * g + 4];
        p.b3[g] = (const float*)d_in[1 + 6 * g + 5];
    }
    int B = in_sizes[0] / (21 * D);

    size_t smem = SMEM_FLOATS * sizeof(float);   // 204800 bytes
    cudaFuncSetAttribute(mp_mlp_kernel,
                         cudaFuncAttributeMaxDynamicSharedMemorySize, (int)smem);

    dim3 grid(B / TB, 21);
    mp_mlp_kernel<<<grid, THREADS, smem>>>(x, p, (float*)d_out, B);
}

// round 7
// speedup vs baseline: 3.9133x; 2.9627x over previous
#include <cuda_runtime.h>
#include <cuda_bf16.h>
#include <stdint.h>

// ============================================================
// Legacy-HMMA (mma.sync m16n8k16 bf16) fused 3-layer MLP.
//  - bf16 2-way split (hi/lo) of activations and weights;
//    C += Ah*Bh + Al*Bh + Ah*Bl  in fp32 accumulators.
//  - Hidden activations stay in registers: C-fragment layout of
//    layer l == A-fragment layout of layer l+1 (no smem, no syncs).
//  - Weights pre-packed by a prep kernel into lane-indexed uint4
//    fragment images {b0h,b1h,b0l,b1l} -> one LDG.128 per 3 MMAs.
// ============================================================

#define W2OFF 141312u   // uint4 offsets into g_wbuf
#define W3OFF 227328u
__device__ uint4 g_wbuf[270336];   // 4.33 MB

struct NodeInfo { int gi, row, n, out, nb[6]; };
__constant__ NodeInfo c_nodes[21] = {
    {0,0,6, 0,{0,1,5,9,13,17}},
    {1,0,5, 5,{0,5,6,1,9,0}},
    {1,1,5, 9,{0,9,10,5,13,0}},
    {1,2,5,13,{0,13,14,9,17,0}},
    {2,0,4, 1,{0,1,2,5,0,0}},
    {2,1,4,17,{0,17,18,13,0,0}},
    {3,0,3, 2,{1,2,3,0,0,0}},
    {3,1,3, 3,{2,3,4,0,0,0}},
    {3,2,3, 6,{5,6,7,0,0,0}},
    {3,3,3, 7,{6,7,8,0,0,0}},
    {3,4,3,10,{9,10,11,0,0,0}},
    {3,5,3,11,{10,11,12,0,0,0}},
    {3,6,3,14,{13,14,15,0,0,0}},
    {3,7,3,15,{14,15,16,0,0,0}},
    {3,8,3,18,{17,18,19,0,0,0}},
    {3,9,3,19,{18,19,20,0,0,0}},
    {4,0,2, 4,{3,4,0,0,0,0}},
    {4,1,2, 8,{7,8,0,0,0,0}},
    {4,2,2,12,{11,12,0,0,0,0}},
    {4,3,2,16,{15,16,0,0,0,0}},
    {4,4,2,20,{19,20,0,0,0,0}},
};
__constant__ int c_offs1[21] = {0,6,11,16,21,25,29,32,35,38,41,44,47,50,53,56,59,61,63,65,67};

struct WPtrs { const float* w1[5]; const float* w2[5]; const float* w3[5]; };
struct BPtrs { const float* b1[5]; const float* b2[5]; const float* b3[5]; };

// pack (f0,f1) into hi-bf16x2 / lo-bf16x2 (f0 in low half)
__device__ __forceinline__ void hilo2(float f0, float f1, uint32_t& hi, uint32_t& lo) {
    __nv_bfloat16 h0 = __float2bfloat16(f0), h1 = __float2bfloat16(f1);
    hi = (uint32_t)__bfloat16_as_ushort(h0) | ((uint32_t)__bfloat16_as_ushort(h1) << 16);
    float r0 = f0 - __bfloat162float(h0), r1 = f1 - __bfloat162float(h1);
    __nv_bfloat16 l0 = __float2bfloat16(r0), l1 = __float2bfloat16(r1);
    lo = (uint32_t)__bfloat16_as_ushort(l0) | ((uint32_t)__bfloat16_as_ushort(l1) << 16);
}

__device__ __forceinline__ void mma_bf16(float* c, const uint32_t* a,
                                         uint32_t b0, uint32_t b1) {
    asm volatile(
        "mma.sync.aligned.m16n8k16.row.col.f32.bf16.bf16.f32 "
        "{%0,%1,%2,%3}, {%4,%5,%6,%7}, {%8,%9}, {%0,%1,%2,%3};"
        : "+f"(c[0]), "+f"(c[1]), "+f"(c[2]), "+f"(c[3])
        : "r"(a[0]), "r"(a[1]), "r"(a[2]), "r"(a[3]), "r"(b0), "r"(b1));
}

// ============================================================
// prep kernel: split weights into bf16 hi/lo B-fragment images.
// blob index: ((kt*NT + nt)*32 + lane), value uint4{b0h,b1h,b0l,b1l}
// b0 = W[k0..k0+1][n], b1 = W[k0+8..k0+9][n], k0 = kt*16+2t, n = nt*8+g
// ============================================================
__global__ void prep_kernel(WPtrs wp)
{
    const int node = blockIdx.x, tid = threadIdx.x;
    const NodeInfo& nd = c_nodes[node];

    {   // W1: [n*64, 128], NT=16, KT=4n
        const float* W = wp.w1[nd.gi] + (size_t)nd.row * nd.n * 64 * 128;
        uint4* dst = g_wbuf + (size_t)c_offs1[node] * 2048;
        const int tot = nd.n * 2048;
        for (int i = tid; i < tot; i += blockDim.x) {
            int lane = i & 31, idx = i >> 5, nt = idx & 15, kt = idx >> 4;
            int g = lane >> 2, t = lane & 3;
            int n = nt * 8 + g, k0 = kt * 16 + 2 * t;
            float a0 = W[(size_t)k0 * 128 + n],       a1 = W[(size_t)(k0 + 1) * 128 + n];
            float a2 = W[(size_t)(k0 + 8) * 128 + n], a3 = W[(size_t)(k0 + 9) * 128 + n];
            uint4 v;
            hilo2(a0, a1, v.x, v.z);
            hilo2(a2, a3, v.y, v.w);
            dst[i] = v;
        }
    }
    {   // W2: [128,128], NT=16, KT=8
        const float* W = wp.w2[nd.gi] + (size_t)nd.row * 128 * 128;
        uint4* dst = g_wbuf + W2OFF + (size_t)node * 4096;
        for (int i = tid; i < 4096; i += blockDim.x) {
            int lane = i & 31, idx = i >> 5, nt = idx & 15, kt = idx >> 4;
            int g = lane >> 2, t = lane & 3;
            int n = nt * 8 + g, k0 = kt * 16 + 2 * t;
            float a0 = W[(size_t)k0 * 128 + n],       a1 = W[(size_t)(k0 + 1) * 128 + n];
            float a2 = W[(size_t)(k0 + 8) * 128 + n], a3 = W[(size_t)(k0 + 9) * 128 + n];
            uint4 v;
            hilo2(a0, a1, v.x, v.z);
            hilo2(a2, a3, v.y, v.w);
            dst[i] = v;
        }
    }
    {   // W3: [128,64], NT=8, KT=8
        const float* W = wp.w3[nd.gi] + (size_t)nd.row * 128 * 64;
        uint4* dst = g_wbuf + W3OFF + (size_t)node * 2048;
        for (int i = tid; i < 2048; i += blockDim.x) {
            int lane = i & 31, idx = i >> 5, nt = idx & 7, kt = idx >> 3;
            int g = lane >> 2, t = lane & 3;
            int n = nt * 8 + g, k0 = kt * 16 + 2 * t;
            float a0 = W[(size_t)k0 * 64 + n],       a1 = W[(size_t)(k0 + 1) * 64 + n];
            float a2 = W[(size_t)(k0 + 8) * 64 + n], a3 = W[(size_t)(k0 + 9) * 64 + n];
            uint4 v;
            hilo2(a0, a1, v.x, v.z);
            hilo2(a2, a3, v.y, v.w);
            dst[i] = v;
        }
    }
}

// ============================================================
// main kernel: 256 threads = 8 warps, each warp M=16 rows; TB=128.
// grid = (21 nodes, B/128)
// ============================================================
__global__ void __launch_bounds__(256, 1)
mp_mma_kernel(const float* __restrict__ x, BPtrs bp, float* __restrict__ out)
{
    const int tid = threadIdx.x;
    const int wid = tid >> 5, lane = tid & 31;
    const int g = lane >> 2, t = lane & 3;
    const int node = blockIdx.x;
    const NodeInfo& nd = c_nodes[node];
    const int r0 = blockIdx.y * 128 + wid * 16 + g;   // rows r0 / r0+8

    float C[16][4];
    #pragma unroll
    for (int i = 0; i < 16; ++i)
        C[i][0] = C[i][1] = C[i][2] = C[i][3] = 0.f;

    // ---------------- layer 1 ----------------
    const uint4* __restrict__ W1b = g_wbuf + (size_t)c_offs1[node] * 2048 + lane;
    const int NK = nd.n * 4;
    float2 f0, f1, f2, f3;
    {   // prefetch k-group 0
        const float* p = x + (size_t)r0 * 1344 + nd.nb[0] * 64 + 2 * t;
        f0 = *(const float2*)(p);
        f1 = *(const float2*)(p + 8 * 1344);
        f2 = *(const float2*)(p + 8);
        f3 = *(const float2*)(p + 8 * 1344 + 8);
    }
    for (int kg = 0; kg < NK; ++kg) {
        float2 n0 = f0, n1 = f1, n2 = f2, n3 = f3;
        int nxt = kg + 1;
        if (nxt < NK) {   // prefetch next k-group while current mmas run
            const float* p = x + (size_t)r0 * 1344 + nd.nb[nxt >> 2] * 64
                             + (nxt & 3) * 16 + 2 * t;
            f0 = *(const float2*)(p);
            f1 = *(const float2*)(p + 8 * 1344);
            f2 = *(const float2*)(p + 8);
            f3 = *(const float2*)(p + 8 * 1344 + 8);
        }
        uint32_t ah[4], al[4];
        hilo2(n0.x, n0.y, ah[0], al[0]);
        hilo2(n1.x, n1.y, ah[1], al[1]);
        hilo2(n2.x, n2.y, ah[2], al[2]);
        hilo2(n3.x, n3.y, ah[3], al[3]);
        const uint4* wr = W1b + (size_t)kg * 512;
        #pragma unroll
        for (int nt = 0; nt < 16; ++nt) {
            uint4 b = wr[nt * 32];
            mma_bf16(C[nt], ah, b.x, b.y);
            mma_bf16(C[nt], al, b.x, b.y);
            mma_bf16(C[nt], ah, b.z, b.w);
        }
    }

    // epilogue 1: bias + relu -> next-layer A fragments (registers only)
    uint32_t Ah[8][4], Al[8][4];
    {
        const float* B1 = bp.b1[nd.gi] + nd.row * 128;
        #pragma unroll
        for (int nt = 0; nt < 16; ++nt) {
            float2 bv = *(const float2*)(B1 + nt * 8 + 2 * t);
            float v0 = fmaxf(C[nt][0] + bv.x, 0.f);
            float v1 = fmaxf(C[nt][1] + bv.y, 0.f);
            float v2 = fmaxf(C[nt][2] + bv.x, 0.f);
            float v3 = fmaxf(C[nt][3] + bv.y, 0.f);
            const int kt = nt >> 1, h = (nt & 1) * 2;
            hilo2(v0, v1, Ah[kt][h],     Al[kt][h]);
            hilo2(v2, v3, Ah[kt][h + 1], Al[kt][h + 1]);
        }
    }

    // ---------------- layer 2 ----------------
    #pragma unroll
    for (int i = 0; i < 16; ++i)
        C[i][0] = C[i][1] = C[i][2] = C[i][3] = 0.f;
    {
        const uint4* __restrict__ W2b = g_wbuf + W2OFF + (size_t)node * 4096 + lane;
        #pragma unroll
        for (int kt = 0; kt < 8; ++kt) {
            const uint4* wr = W2b + kt * 512;
            #pragma unroll
            for (int nt = 0; nt < 16; ++nt) {
                uint4 b = wr[nt * 32];
                mma_bf16(C[nt], Ah[kt], b.x, b.y);
                mma_bf16(C[nt], Al[kt], b.x, b.y);
                mma_bf16(C[nt], Ah[kt], b.z, b.w);
            }
        }
    }

    // epilogue 2
    {
        const float* B2 = bp.b2[nd.gi] + nd.row * 128;
        #pragma unroll
        for (int nt = 0; nt < 16; ++nt) {
            float2 bv = *(const float2*)(B2 + nt * 8 + 2 * t);
            float v0 = fmaxf(C[nt][0] + bv.x, 0.f);
            float v1 = fmaxf(C[nt][1] + bv.y, 0.f);
            float v2 = fmaxf(C[nt][2] + bv.x, 0.f);
            float v3 = fmaxf(C[nt][3] + bv.y, 0.f);
            const int kt = nt >> 1, h = (nt & 1) * 2;
            hilo2(v0, v1, Ah[kt][h],     Al[kt][h]);
            hilo2(v2, v3, Ah[kt][h + 1], Al[kt][h + 1]);
        }
    }

    // ---------------- layer 3 ----------------
    #pragma unroll
    for (int i = 0; i < 8; ++i)
        C[i][0] = C[i][1] = C[i][2] = C[i][3] = 0.f;
    {
        const uint4* __restrict__ W3b = g_wbuf + W3OFF + (size_t)node * 2048 + lane;
        #pragma unroll
        for (int kt = 0; kt < 8; ++kt) {
            const uint4* wr = W3b + kt * 256;
            #pragma unroll
            for (int nt = 0; nt < 8; ++nt) {
                uint4 b = wr[nt * 32];
                mma_bf16(C[nt], Ah[kt], b.x, b.y);
                mma_bf16(C[nt], Al[kt], b.x, b.y);
                mma_bf16(C[nt], Ah[kt], b.z, b.w);
            }
        }
    }

    // output epilogue
    {
        const float* B3 = bp.b3[nd.gi] + nd.row * 64;
        float* o0 = out + (size_t)r0 * 1344 + nd.out * 64 + 2 * t;
        #pragma unroll
        for (int nt = 0; nt < 8; ++nt) {
            float2 bv = *(const float2*)(B3 + nt * 8 + 2 * t);
            *(float2*)(o0 + nt * 8) =
                make_float2(C[nt][0] + bv.x, C[nt][1] + bv.y);
            *(float2*)(o0 + nt * 8 + 8 * 1344) =
                make_float2(C[nt][2] + bv.x, C[nt][3] + bv.y);
        }
    }
}

// ============================================================
extern "C" void kernel_launch(void* const* d_in, const int* in_sizes, int n_in,
                              void* d_out, int out_size)
{
    const float* x = (const float*)d_in[0];
    WPtrs wp; BPtrs bp;
    for (int g = 0; g < 5; ++g) {
        wp.w1[g] = (const float*)d_in[1 + 6*g + 0];
        bp.b1[g] = (const float*)d_in[1 + 6*g + 1];
        wp.w2[g] = (const float*)d_in[1 + 6*g + 2];
        bp.b2[g] = (const float*)d_in[1 + 6*g + 3];
        wp.w3[g] = (const float*)d_in[1 + 6*g + 4];
        bp.b3[g] = (const float*)d_in[1 + 6*g + 5];
    }
    int B = in_sizes[0] / (21 * 64);

    prep_kernel<<<21, 256>>>(wp);

    dim3 grid(21, B / 128);
    mp_mma_kernel<<<grid, 256>>>(x, bp, (float*)d_out);
}